// round 10
// baseline (speedup 1.0000x reference)
#include <cuda_runtime.h>
#include <cuda_bf16.h>
#include <math.h>
#include <stdint.h>

// Problem constants
#define B_SZ    4096
#define N_IN    7
#define PC_DIM  256
#define K_CAPS  25
#define MC_DIM  128
#define KM      (K_CAPS * MC_DIM)      // 3200
#define VOTES_PER_B (N_IN * KM)        // 22400
#define POSE_STRIDE (N_IN * PC_DIM)    // 1792
#define LN_EPS  1e-5f
#define AGREE_SCALE 0.08838834764831845f   // 1/sqrt(128)

// scratch
__device__ float g_votes[(size_t)B_SZ * VOTES_PER_B];                 // 367 MB
__device__ __nv_bfloat16 g_pa_hi[(size_t)B_SZ * POSE_STRIDE];         // 14.7 MB
__device__ __nv_bfloat16 g_pa_lo[(size_t)B_SZ * POSE_STRIDE];
// transposed weights: wt[n][km][d], d contiguous
__device__ __nv_bfloat16 g_wt_hi[(size_t)N_IN * KM * PC_DIM];         // 11.5 MB
__device__ __nv_bfloat16 g_wt_lo[(size_t)N_IN * KM * PC_DIM];

// ---------------- helpers ----------------
__device__ __forceinline__ void mma_bf16(float& c0, float& c1, float& c2, float& c3,
                                         unsigned a0, unsigned a1, unsigned a2, unsigned a3,
                                         unsigned b0, unsigned b1) {
    asm volatile(
        "mma.sync.aligned.m16n8k16.row.col.f32.bf16.bf16.f32 "
        "{%0,%1,%2,%3}, {%4,%5,%6,%7}, {%8,%9}, {%0,%1,%2,%3};\n"
        : "+f"(c0), "+f"(c1), "+f"(c2), "+f"(c3)
        : "r"(a0), "r"(a1), "r"(a2), "r"(a3), "r"(b0), "r"(b1));
}
__device__ __forceinline__ void ldmatrix_x4(unsigned& r0, unsigned& r1,
                                            unsigned& r2, unsigned& r3, uint32_t addr) {
    asm volatile("ldmatrix.sync.aligned.m8n8.x4.shared.b16 {%0,%1,%2,%3}, [%4];"
                 : "=r"(r0), "=r"(r1), "=r"(r2), "=r"(r3) : "r"(addr));
}
__device__ __forceinline__ void cp_async16(uint32_t dst, const void* src) {
    asm volatile("cp.async.cg.shared.global [%0], [%1], 16;\n" :: "r"(dst), "l"(src));
}
__device__ __forceinline__ void cp_commit() { asm volatile("cp.async.commit_group;\n"); }
__device__ __forceinline__ void cp_wait0() { asm volatile("cp.async.wait_group 0;\n" ::: "memory"); }
__device__ __forceinline__ void cp_wait1() { asm volatile("cp.async.wait_group 1;\n" ::: "memory"); }

__device__ __forceinline__ float warp_sum(float v) {
    #pragma unroll
    for (int o = 16; o; o >>= 1) v += __shfl_xor_sync(0xffffffffu, v, o);
    return v;
}
__device__ __forceinline__ float warp_max(float v) {
    #pragma unroll
    for (int o = 16; o; o >>= 1) v = fmaxf(v, __shfl_xor_sync(0xffffffffu, v, o));
    return v;
}
__device__ __forceinline__ uint32_t smem_u32(const void* p) {
    return (uint32_t)__cvta_generic_to_shared(p);
}

// ---------------------------------------------------------------------------
// Decompose poses: x -> bf16 hi + lo
// ---------------------------------------------------------------------------
__global__ __launch_bounds__(256) void decomp_poses_kernel(
    const float* __restrict__ poses,
    __nv_bfloat16* __restrict__ hi, __nv_bfloat16* __restrict__ lo)
{
    const int i = blockIdx.x * 256 + threadIdx.x;
    const int n2 = B_SZ * POSE_STRIDE / 2;
    if (i >= n2) return;
    const float2 x = ((const float2*)poses)[i];
    const __nv_bfloat16 h0 = __float2bfloat16(x.x);
    const __nv_bfloat16 h1 = __float2bfloat16(x.y);
    const __nv_bfloat16 l0 = __float2bfloat16(x.x - __bfloat162float(h0));
    const __nv_bfloat16 l1 = __float2bfloat16(x.y - __bfloat162float(h1));
    ((__nv_bfloat162*)hi)[i] = __nv_bfloat162(h0, h1);
    ((__nv_bfloat162*)lo)[i] = __nv_bfloat162(l0, l1);
}

// ---------------------------------------------------------------------------
// Decompose + transpose w: w[n][d][km] f32 -> wt[n][km][d] bf16 hi/lo
// ---------------------------------------------------------------------------
__global__ __launch_bounds__(256) void decomp_wt_kernel(
    const float* __restrict__ w,
    __nv_bfloat16* __restrict__ hi, __nv_bfloat16* __restrict__ lo)
{
    __shared__ float tile[32][33];
    const int tx = threadIdx.x, ty = threadIdx.y;
    const int km0 = blockIdx.x * 32, d0 = blockIdx.y * 32, n = blockIdx.z;
    #pragma unroll
    for (int j = 0; j < 4; j++) {
        const int d = d0 + ty + 8 * j;
        tile[ty + 8 * j][tx] = w[((size_t)n * PC_DIM + d) * KM + km0 + tx];
    }
    __syncthreads();
    #pragma unroll
    for (int j = 0; j < 4; j++) {
        const int km = km0 + ty + 8 * j;
        const float x = tile[tx][ty + 8 * j];
        const __nv_bfloat16 h = __float2bfloat16(x);
        const __nv_bfloat16 l = __float2bfloat16(x - __bfloat162float(h));
        const size_t o = ((size_t)n * KM + km) * PC_DIM + d0 + tx;
        hi[o] = h;
        lo[o] = l;
    }
}

// ---------------------------------------------------------------------------
// Kernel A: bf16 3-term split GEMM, mma.sync + ldmatrix.
// Uniform 12-slice pipeline: slice s = (kc, term), kc=s/3, term=s%3:
//   term0 (Ah,Bh), term1 (Ah,Bl), term2 (Al,Bh), each a 64-K chunk.
// Each slice stages its own A+B tile pair (double-buffered).
// grid (25, 32, 7), 256 threads, warp grid 2(M)x4(N), warp tile 64x32.
// ---------------------------------------------------------------------------
#define PITCH 72                        // bf16 per smem row (144 B)
#define TILE_BYTES (128 * PITCH * 2)    // 18432
#define SLICE_BYTES (2 * TILE_BYTES)    // A + B
#define VOTES_SMEM (2 * SLICE_BYTES)    // 73728

__global__ __launch_bounds__(256, 2) void votes_hmma_kernel(
    const __nv_bfloat16* __restrict__ pa_hi,
    const __nv_bfloat16* __restrict__ pa_lo,
    const __nv_bfloat16* __restrict__ wt_hi,
    const __nv_bfloat16* __restrict__ wt_lo)
{
    extern __shared__ __nv_bfloat16 smem[];
    const uint32_t base = smem_u32(smem);

    const int tid  = threadIdx.x;
    const int lane = tid & 31;
    const int wrp  = tid >> 5;
    const int wm   = wrp >> 2;        // 0..1
    const int wn   = wrp & 3;         // 0..3

    const int tn = blockIdx.x;        // 0..24
    const int tm = blockIdx.y;        // 0..31
    const int n  = blockIdx.z;        // 0..6

    // per-thread lane offsets (elements) for ldmatrix
    const int a_off = (((lane & 7) | (((lane >> 3) & 1) << 3)) * PITCH)
                    + ((lane >> 4) << 3) + wm * 64 * PITCH;
    const int b_off = (((lane & 7) | (((lane >> 4) & 1) << 3)) * PITCH)
                    + (((lane >> 3) & 1) << 3) + wn * 32 * PITCH;

    const __nv_bfloat16* Abase_h = pa_hi + (size_t)(tm * 128) * POSE_STRIDE + n * PC_DIM;
    const __nv_bfloat16* Abase_l = pa_lo + (size_t)(tm * 128) * POSE_STRIDE + n * PC_DIM;
    const __nv_bfloat16* Bbase_h = wt_hi + ((size_t)n * KM + tn * 128) * PC_DIM;
    const __nv_bfloat16* Bbase_l = wt_lo + ((size_t)n * KM + tn * 128) * PC_DIM;

    // stage slice s into buffer buf: A tile + B tile, one commit
    auto stage = [&](int buf, int s) {
        const int kc = s / 3, t = s % 3;
        const __nv_bfloat16* As = (t == 2) ? Abase_l : Abase_h;
        const __nv_bfloat16* Bs = (t == 1) ? Bbase_l : Bbase_h;
        const uint32_t dA = base + (uint32_t)buf * SLICE_BYTES;
        const uint32_t dB = dA + TILE_BYTES;
        #pragma unroll
        for (int i = 0; i < 4; i++) {
            const int idx = tid + 256 * i;
            const int r = idx >> 3, c = idx & 7;
            const uint32_t off = (uint32_t)(r * PITCH * 2 + c * 16);
            cp_async16(dA + off, As + (size_t)r * POSE_STRIDE + kc * 64 + c * 8);
            cp_async16(dB + off, Bs + (size_t)r * PC_DIM     + kc * 64 + c * 8);
        }
        cp_commit();
    };

    float acc[4][4][4];
    #pragma unroll
    for (int mi = 0; mi < 4; mi++)
        #pragma unroll
        for (int ni = 0; ni < 4; ni++)
            #pragma unroll
            for (int c = 0; c < 4; c++) acc[mi][ni][c] = 0.f;

    stage(0, 0);

    #pragma unroll 1
    for (int s = 0; s < 12; ++s) {
        if (s < 11) stage((s + 1) & 1, s + 1);
        if (s < 11) cp_wait1(); else cp_wait0();
        __syncthreads();

        const uint32_t Aslot = base + (uint32_t)(s & 1) * SLICE_BYTES;
        const uint32_t Bslot = Aslot + TILE_BYTES;

        #pragma unroll
        for (int ks = 0; ks < 4; ks++) {
            unsigned af[4][4];
            #pragma unroll
            for (int mi = 0; mi < 4; mi++)
                ldmatrix_x4(af[mi][0], af[mi][1], af[mi][2], af[mi][3],
                            Aslot + 2u * (uint32_t)(a_off + mi * 16 * PITCH + ks * 16));
            unsigned bf[4][2];
            #pragma unroll
            for (int p = 0; p < 2; p++)
                ldmatrix_x4(bf[2*p][0], bf[2*p][1], bf[2*p+1][0], bf[2*p+1][1],
                            Bslot + 2u * (uint32_t)(b_off + p * 16 * PITCH + ks * 16));
            #pragma unroll
            for (int mi = 0; mi < 4; mi++)
                #pragma unroll
                for (int ni = 0; ni < 4; ni++)
                    mma_bf16(acc[mi][ni][0], acc[mi][ni][1], acc[mi][ni][2], acc[mi][ni][3],
                             af[mi][0], af[mi][1], af[mi][2], af[mi][3],
                             bf[ni][0], bf[ni][1]);
        }
        __syncthreads();
    }

    // epilogue (canonical D fragment layout)
    const int grp = lane >> 2, tig = lane & 3;
    #pragma unroll
    for (int mi = 0; mi < 4; mi++) {
        const int row = tm * 128 + wm * 64 + mi * 16 + grp;
        #pragma unroll
        for (int ni = 0; ni < 4; ni++) {
            const int col = tn * 128 + wn * 32 + ni * 8 + 2 * tig;
            float* p0 = g_votes + (size_t)row * VOTES_PER_B + n * KM + col;
            float* p1 = g_votes + (size_t)(row + 8) * VOTES_PER_B + n * KM + col;
            *(float2*)p0 = make_float2(acc[mi][ni][0], acc[mi][ni][1]);
            *(float2*)p1 = make_float2(acc[mi][ni][2], acc[mi][ni][3]);
        }
    }
}

// ---------------------------------------------------------------------------
// Kernel B: register-resident routing with cp.async sample prefetch.
// 148 CTAs x 800 threads (25 warps). Double-buffered smem votes (2x89.6KB).
// ---------------------------------------------------------------------------
#define RT_GRID 148
#define RT_SMEM (2 * VOTES_PER_B * 4)   // 179200 B

__global__ __launch_bounds__(800, 1) void routing_kernel(
    const float* __restrict__ acts_prior,
    const float* __restrict__ ln_gamma,
    const float* __restrict__ ln_beta,
    const float* __restrict__ cls_weight,
    const float* __restrict__ cls_bias,
    float* __restrict__ out)
{
    extern __shared__ float rsmem[];    // 2 x VOTES_PER_B
    __shared__ float sa[8];
    __shared__ float sagree[184];
    __shared__ float sra[184];

    const int tid  = threadIdx.x;
    const int wrp  = tid >> 5;
    const int lane = tid & 31;
    const int k    = wrp;

    const float4 g4  = *(const float4*)&ln_gamma[lane * 4];
    const float4 b4  = *(const float4*)&ln_beta[lane * 4];
    const float4 cw4 = *(const float4*)&cls_weight[k * MC_DIM + lane * 4];
    const float  bias = cls_bias[k];

    const uint32_t sv = smem_u32(rsmem);

    auto stage = [&](int buf, int b) {
        const float* src = g_votes + (size_t)b * VOTES_PER_B;
        const uint32_t dst = sv + (uint32_t)buf * (VOTES_PER_B * 4);
        #pragma unroll
        for (int i = 0; i < 7; i++) {
            const int idx = tid + i * 800;    // 5600 float4 total
            cp_async16(dst + (uint32_t)idx * 16, src + idx * 4);
        }
        cp_commit();
    };

    stage(0, blockIdx.x);

    int buf = 0;
    #pragma unroll 1
    for (int b = blockIdx.x; b < B_SZ; b += RT_GRID, buf ^= 1) {
        if (tid < N_IN) sa[tid] = acts_prior[(size_t)b * N_IN + tid];
        if (b + RT_GRID < B_SZ) { stage(buf ^ 1, b + RT_GRID); cp_wait1(); }
        else cp_wait0();
        __syncthreads();

        // copy this sample's votes slice smem -> regs
        float4 v[N_IN];
        {
            const float* vb = rsmem + buf * VOTES_PER_B + k * MC_DIM + lane * 4;
            #pragma unroll
            for (int n = 0; n < N_IN; n++)
                v[n] = *(const float4*)(vb + n * KM);
        }

        float ra[N_IN];
        #pragma unroll
        for (int n = 0; n < N_IN; n++) ra[n] = sa[n] * (1.f / 25.f);

        float4 pose;
        #pragma unroll 1
        for (int it = 0; it < 3; ++it) {
            if (it > 0) {
                #pragma unroll
                for (int n = 0; n < N_IN; n++) {
                    float d = v[n].x * pose.x + v[n].y * pose.y
                            + v[n].z * pose.z + v[n].w * pose.w;
                    d = warp_sum(d);
                    if (lane == 0) sagree[n * K_CAPS + k] = d * AGREE_SCALE;
                }
                __syncthreads();
                if (wrp < N_IN) {
                    const float x = (lane < K_CAPS) ? sagree[wrp * K_CAPS + lane] : -1e30f;
                    const float mx = warp_max(x);
                    const float e = (lane < K_CAPS) ? __expf(x - mx) : 0.f;
                    const float ssum = warp_sum(e);
                    if (lane < K_CAPS) {
                        const float r = e / ssum;
                        sra[wrp * K_CAPS + lane] = r * sa[wrp];
                        if (it == 2)
                            out[(size_t)B_SZ * K_CAPS + (size_t)b * 175
                                + wrp * K_CAPS + lane] = r;
                    }
                }
                __syncthreads();
                #pragma unroll
                for (int n = 0; n < N_IN; n++) ra[n] = sra[n * K_CAPS + k];
            }
            pose = make_float4(0.f, 0.f, 0.f, 0.f);
            #pragma unroll
            for (int n = 0; n < N_IN; n++) {
                pose.x = fmaf(ra[n], v[n].x, pose.x);
                pose.y = fmaf(ra[n], v[n].y, pose.y);
                pose.z = fmaf(ra[n], v[n].z, pose.z);
                pose.w = fmaf(ra[n], v[n].w, pose.w);
            }
            {
                float s = pose.x + pose.y + pose.z + pose.w;
                s = warp_sum(s);
                const float mu = s * (1.f / 128.f);
                float var = (pose.x - mu) * (pose.x - mu) + (pose.y - mu) * (pose.y - mu)
                          + (pose.z - mu) * (pose.z - mu) + (pose.w - mu) * (pose.w - mu);
                var = warp_sum(var) * (1.f / 128.f);
                const float rs = rsqrtf(var + LN_EPS);
                pose.x = (pose.x - mu) * rs * g4.x + b4.x;
                pose.y = (pose.y - mu) * rs * g4.y + b4.y;
                pose.z = (pose.z - mu) * rs * g4.z + b4.z;
                pose.w = (pose.w - mu) * rs * g4.w + b4.w;
            }
        }
        {
            float d = pose.x * cw4.x + pose.y * cw4.y + pose.z * cw4.z + pose.w * cw4.w;
            d = warp_sum(d);
            if (lane == 0) out[(size_t)b * K_CAPS + k] = d + bias;
        }
        __syncthreads();   // all reads of buf done before it is re-staged
    }
}

// ---------------------------------------------------------------------------
extern "C" void kernel_launch(void* const* d_in, const int* in_sizes, int n_in,
                              void* d_out, int out_size)
{
    (void)in_sizes; (void)n_in; (void)out_size;
    const float* poses = (const float*)d_in[0];
    const float* acts  = (const float*)d_in[1];
    const float* w     = (const float*)d_in[2];
    const float* gamma = (const float*)d_in[3];
    const float* beta  = (const float*)d_in[4];
    const float* clsw  = (const float*)d_in[5];
    const float* clsb  = (const float*)d_in[6];
    float* out = (float*)d_out;

    __nv_bfloat16 *pa_hi, *pa_lo, *wt_hi, *wt_lo;
    cudaGetSymbolAddress((void**)&pa_hi, g_pa_hi);
    cudaGetSymbolAddress((void**)&pa_lo, g_pa_lo);
    cudaGetSymbolAddress((void**)&wt_hi, g_wt_hi);
    cudaGetSymbolAddress((void**)&wt_lo, g_wt_lo);

    {
        const int n2 = B_SZ * POSE_STRIDE / 2;
        decomp_poses_kernel<<<(n2 + 255) / 256, 256>>>(poses, pa_hi, pa_lo);
        decomp_wt_kernel<<<dim3(KM / 32, PC_DIM / 32, N_IN), dim3(32, 8)>>>(w, wt_hi, wt_lo);
    }

    cudaFuncSetAttribute(votes_hmma_kernel,
                         cudaFuncAttributeMaxDynamicSharedMemorySize,
                         VOTES_SMEM);
    votes_hmma_kernel<<<dim3(25, 32, 7), 256, VOTES_SMEM>>>(pa_hi, pa_lo, wt_hi, wt_lo);

    cudaFuncSetAttribute(routing_kernel,
                         cudaFuncAttributeMaxDynamicSharedMemorySize,
                         RT_SMEM);
    routing_kernel<<<RT_GRID, 800, RT_SMEM>>>(acts, gamma, beta, clsw, clsb, out);
}

// round 11
// speedup vs baseline: 1.0899x; 1.0899x over previous
#include <cuda_runtime.h>
#include <cuda_bf16.h>
#include <math.h>
#include <stdint.h>

// Problem constants
#define B_SZ    4096
#define N_IN    7
#define PC_DIM  256
#define K_CAPS  25
#define MC_DIM  128
#define KM      (K_CAPS * MC_DIM)      // 3200
#define VOTES_PER_B (N_IN * KM)        // 22400
#define POSE_STRIDE (N_IN * PC_DIM)    // 1792
#define LN_EPS  1e-5f
#define AGREE_SCALE 0.08838834764831845f   // 1/sqrt(128)

// scratch
__device__ float g_votes[(size_t)B_SZ * VOTES_PER_B];                 // 367 MB
__device__ __nv_bfloat16 g_pa_hi[(size_t)B_SZ * POSE_STRIDE];         // 14.7 MB
__device__ __nv_bfloat16 g_pa_lo[(size_t)B_SZ * POSE_STRIDE];
// transposed weights: wt[n][km][d], d contiguous
__device__ __nv_bfloat16 g_wt_hi[(size_t)N_IN * KM * PC_DIM];         // 11.5 MB
__device__ __nv_bfloat16 g_wt_lo[(size_t)N_IN * KM * PC_DIM];

// ---------------- helpers ----------------
__device__ __forceinline__ void mma_bf16(float& c0, float& c1, float& c2, float& c3,
                                         unsigned a0, unsigned a1, unsigned a2, unsigned a3,
                                         unsigned b0, unsigned b1) {
    asm volatile(
        "mma.sync.aligned.m16n8k16.row.col.f32.bf16.bf16.f32 "
        "{%0,%1,%2,%3}, {%4,%5,%6,%7}, {%8,%9}, {%0,%1,%2,%3};\n"
        : "+f"(c0), "+f"(c1), "+f"(c2), "+f"(c3)
        : "r"(a0), "r"(a1), "r"(a2), "r"(a3), "r"(b0), "r"(b1));
}
__device__ __forceinline__ void ldmatrix_x4(unsigned& r0, unsigned& r1,
                                            unsigned& r2, unsigned& r3, uint32_t addr) {
    asm volatile("ldmatrix.sync.aligned.m8n8.x4.shared.b16 {%0,%1,%2,%3}, [%4];"
                 : "=r"(r0), "=r"(r1), "=r"(r2), "=r"(r3) : "r"(addr));
}
__device__ __forceinline__ void cp_async16(uint32_t dst, const void* src) {
    asm volatile("cp.async.cg.shared.global [%0], [%1], 16;\n" :: "r"(dst), "l"(src));
}
__device__ __forceinline__ void cp_commit() { asm volatile("cp.async.commit_group;\n"); }
__device__ __forceinline__ void cp_wait0() { asm volatile("cp.async.wait_group 0;\n" ::: "memory"); }
__device__ __forceinline__ void cp_wait1() { asm volatile("cp.async.wait_group 1;\n" ::: "memory"); }
__device__ __forceinline__ void cp_wait3() { asm volatile("cp.async.wait_group 3;\n" ::: "memory"); }

__device__ __forceinline__ float warp_sum(float v) {
    #pragma unroll
    for (int o = 16; o; o >>= 1) v += __shfl_xor_sync(0xffffffffu, v, o);
    return v;
}
__device__ __forceinline__ float warp_max(float v) {
    #pragma unroll
    for (int o = 16; o; o >>= 1) v = fmaxf(v, __shfl_xor_sync(0xffffffffu, v, o));
    return v;
}
__device__ __forceinline__ uint32_t smem_u32(const void* p) {
    return (uint32_t)__cvta_generic_to_shared(p);
}

// ---------------------------------------------------------------------------
// Fused decompose kernel (poses + w-transpose run CONCURRENTLY in one grid).
// Blocks [0, PO_BLKS): poses -> bf16 hi/lo (flat, 2 elems/thread)
// Blocks [PO_BLKS, PO_BLKS+WT_BLKS): w[n][d][km] -> wt[n][km][d] hi/lo
//   (32x32 smem-tile transpose; tx = tid&31, ty = tid>>5)
// ---------------------------------------------------------------------------
#define PO_N2    (B_SZ * POSE_STRIDE / 2)          // 3,670,016
#define PO_BLKS  ((PO_N2 + 255) / 256)             // 14336
#define WT_BLKS  ((KM / 32) * (PC_DIM / 32) * N_IN) // 100*8*7 = 5600

__global__ __launch_bounds__(256) void decomp_fused_kernel(
    const float* __restrict__ poses, const float* __restrict__ w,
    __nv_bfloat16* __restrict__ pa_hi, __nv_bfloat16* __restrict__ pa_lo,
    __nv_bfloat16* __restrict__ wt_hi, __nv_bfloat16* __restrict__ wt_lo)
{
    const int tid = threadIdx.x;
    if (blockIdx.x < PO_BLKS) {
        const int i = blockIdx.x * 256 + tid;
        if (i >= PO_N2) return;
        const float2 x = ((const float2*)poses)[i];
        const __nv_bfloat16 h0 = __float2bfloat16(x.x);
        const __nv_bfloat16 h1 = __float2bfloat16(x.y);
        const __nv_bfloat16 l0 = __float2bfloat16(x.x - __bfloat162float(h0));
        const __nv_bfloat16 l1 = __float2bfloat16(x.y - __bfloat162float(h1));
        ((__nv_bfloat162*)pa_hi)[i] = __nv_bfloat162(h0, h1);
        ((__nv_bfloat162*)pa_lo)[i] = __nv_bfloat162(l0, l1);
    } else {
        __shared__ float tile[32][33];
        const int bid = blockIdx.x - PO_BLKS;
        const int km0 = (bid % (KM / 32)) * 32;
        const int d0  = ((bid / (KM / 32)) % (PC_DIM / 32)) * 32;
        const int n   = bid / ((KM / 32) * (PC_DIM / 32));
        const int tx = tid & 31, ty = tid >> 5;
        #pragma unroll
        for (int j = 0; j < 4; j++) {
            const int d = d0 + ty + 8 * j;
            tile[ty + 8 * j][tx] = w[((size_t)n * PC_DIM + d) * KM + km0 + tx];
        }
        __syncthreads();
        #pragma unroll
        for (int j = 0; j < 4; j++) {
            const int km = km0 + ty + 8 * j;
            const float x = tile[tx][ty + 8 * j];
            const __nv_bfloat16 h = __float2bfloat16(x);
            const __nv_bfloat16 l = __float2bfloat16(x - __bfloat162float(h));
            const size_t o = ((size_t)n * KM + km) * PC_DIM + d0 + tx;
            wt_hi[o] = h;
            wt_lo[o] = l;
        }
    }
}

// ---------------------------------------------------------------------------
// Kernel A (R9 exact): bf16 3-term split GEMM, mma.sync + ldmatrix,
// kc-major tile reuse (minimal 256 KB/CTA staging).
// grid (25, 32, 7), 256 threads, warp grid 2(M)x4(N), warp tile 64x32.
// K=256 in 4 chunks of 64; per chunk load {A_hi, A_lo, B_hi, B_lo} once and
// run 3 passes: (Ah,Bh), (Al,Bh), (Ah,Bl). 6 smem tile slots, 2 CTAs/SM.
// ---------------------------------------------------------------------------
#define PITCH 72                        // bf16 per smem row (144 B, ldmatrix CF)
#define TILE_BYTES (128 * PITCH * 2)    // 18432
#define VOTES_SMEM (6 * TILE_BYTES)     // 110592

__global__ __launch_bounds__(256, 2) void votes_hmma_kernel(
    const __nv_bfloat16* __restrict__ pa_hi,
    const __nv_bfloat16* __restrict__ pa_lo,
    const __nv_bfloat16* __restrict__ wt_hi,
    const __nv_bfloat16* __restrict__ wt_lo)
{
    extern __shared__ __nv_bfloat16 smem[];
    const uint32_t base = smem_u32(smem);
    // slots: A0,A1 (hi parity), A2,A3 (lo parity), BH, BL
    const uint32_t SLOT_BH = base + 4 * TILE_BYTES;
    const uint32_t SLOT_BL = base + 5 * TILE_BYTES;

    const int tid  = threadIdx.x;
    const int lane = tid & 31;
    const int wrp  = tid >> 5;
    const int wm   = wrp >> 2;        // 0..1
    const int wn   = wrp & 3;         // 0..3

    const int tn = blockIdx.x;        // 0..24
    const int tm = blockIdx.y;        // 0..31
    const int n  = blockIdx.z;        // 0..6

    // per-thread lane offsets (elements) for ldmatrix
    const int a_off = (((lane & 7) | (((lane >> 3) & 1) << 3)) * PITCH)
                    + ((lane >> 4) << 3) + wm * 64 * PITCH;
    const int b_off = (((lane & 7) | (((lane >> 4) & 1) << 3)) * PITCH)
                    + (((lane >> 3) & 1) << 3) + wn * 32 * PITCH;

    const __nv_bfloat16* Abase_h = pa_hi + (size_t)(tm * 128) * POSE_STRIDE + n * PC_DIM;
    const __nv_bfloat16* Abase_l = pa_lo + (size_t)(tm * 128) * POSE_STRIDE + n * PC_DIM;
    const __nv_bfloat16* Bbase_h = wt_hi + ((size_t)n * KM + tn * 128) * PC_DIM;
    const __nv_bfloat16* Bbase_l = wt_lo + ((size_t)n * KM + tn * 128) * PC_DIM;

    auto load_tile = [&](uint32_t dst, const __nv_bfloat16* src, int stride, int kc) {
        const __nv_bfloat16* s = src + kc * 64;
        #pragma unroll
        for (int i = 0; i < 4; i++) {
            const int idx = tid + 256 * i;
            const int r = idx >> 3, c = idx & 7;
            cp_async16(dst + (uint32_t)(r * PITCH * 2 + c * 16),
                       s + (size_t)r * stride + c * 8);
        }
        cp_commit();
    };

    float acc[4][4][4];
    #pragma unroll
    for (int mi = 0; mi < 4; mi++)
        #pragma unroll
        for (int ni = 0; ni < 4; ni++)
            #pragma unroll
            for (int c = 0; c < 4; c++) acc[mi][ni][c] = 0.f;

    auto pass = [&](uint32_t Aslot, uint32_t Bslot) {
        #pragma unroll
        for (int ks = 0; ks < 4; ks++) {
            unsigned af[4][4];
            #pragma unroll
            for (int mi = 0; mi < 4; mi++)
                ldmatrix_x4(af[mi][0], af[mi][1], af[mi][2], af[mi][3],
                            Aslot + 2u * (uint32_t)(a_off + mi * 16 * PITCH + ks * 16));
            unsigned bf[4][2];
            #pragma unroll
            for (int p = 0; p < 2; p++)
                ldmatrix_x4(bf[2*p][0], bf[2*p][1], bf[2*p+1][0], bf[2*p+1][1],
                            Bslot + 2u * (uint32_t)(b_off + p * 16 * PITCH + ks * 16));
            #pragma unroll
            for (int mi = 0; mi < 4; mi++)
                #pragma unroll
                for (int ni = 0; ni < 4; ni++)
                    mma_bf16(acc[mi][ni][0], acc[mi][ni][1], acc[mi][ni][2], acc[mi][ni][3],
                             af[mi][0], af[mi][1], af[mi][2], af[mi][3],
                             bf[ni][0], bf[ni][1]);
        }
    };

    // prologue: kc=0 tiles
    load_tile(base + 0 * TILE_BYTES, Abase_h, POSE_STRIDE, 0);
    load_tile(base + 2 * TILE_BYTES, Abase_l, POSE_STRIDE, 0);
    load_tile(SLOT_BH, Bbase_h, PC_DIM, 0);
    load_tile(SLOT_BL, Bbase_l, PC_DIM, 0);

    #pragma unroll 1
    for (int kc = 0; kc < 4; ++kc) {
        const uint32_t A_hi = base + (uint32_t)(kc & 1) * TILE_BYTES;
        const uint32_t A_lo = base + (uint32_t)(2 + (kc & 1)) * TILE_BYTES;
        if (kc < 3) {
            load_tile(base + (uint32_t)((kc + 1) & 1) * TILE_BYTES, Abase_h, POSE_STRIDE, kc + 1);
            load_tile(base + (uint32_t)(2 + ((kc + 1) & 1)) * TILE_BYTES, Abase_l, POSE_STRIDE, kc + 1);
        }
        if (kc < 3) cp_wait3(); else cp_wait1();
        __syncthreads();

        pass(A_hi, SLOT_BH);   // Ah*Bh
        pass(A_lo, SLOT_BH);   // Al*Bh
        __syncthreads();       // BH fully read

        if (kc < 3) load_tile(SLOT_BH, Bbase_h, PC_DIM, kc + 1);
        if (kc < 3) cp_wait3(); else cp_wait0();
        __syncthreads();

        pass(A_hi, SLOT_BL);   // Ah*Bl
        __syncthreads();       // BL + A slots fully read

        if (kc < 3) load_tile(SLOT_BL, Bbase_l, PC_DIM, kc + 1);
    }

    // epilogue (canonical D fragment layout)
    const int grp = lane >> 2, tig = lane & 3;
    #pragma unroll
    for (int mi = 0; mi < 4; mi++) {
        const int row = tm * 128 + wm * 64 + mi * 16 + grp;
        #pragma unroll
        for (int ni = 0; ni < 4; ni++) {
            const int col = tn * 128 + wn * 32 + ni * 8 + 2 * tig;
            float* p0 = g_votes + (size_t)row * VOTES_PER_B + n * KM + col;
            float* p1 = g_votes + (size_t)(row + 8) * VOTES_PER_B + n * KM + col;
            *(float2*)p0 = make_float2(acc[mi][ni][0], acc[mi][ni][1]);
            *(float2*)p1 = make_float2(acc[mi][ni][2], acc[mi][ni][3]);
        }
    }
}

// ---------------------------------------------------------------------------
// Kernel B (R9 exact): register-resident routing, direct GMEM loads.
// 148 CTAs x 800 threads (25 warps).
// ---------------------------------------------------------------------------
#define RT_GRID 148

__global__ __launch_bounds__(800, 1) void routing_kernel(
    const float* __restrict__ acts_prior,
    const float* __restrict__ ln_gamma,
    const float* __restrict__ ln_beta,
    const float* __restrict__ cls_weight,
    const float* __restrict__ cls_bias,
    float* __restrict__ out)
{
    __shared__ float sa[8];
    __shared__ float sagree[184];
    __shared__ float sra[184];

    const int tid  = threadIdx.x;
    const int wrp  = tid >> 5;
    const int lane = tid & 31;
    const int k    = wrp;

    const float4 g4  = *(const float4*)&ln_gamma[lane * 4];
    const float4 b4  = *(const float4*)&ln_beta[lane * 4];
    const float4 cw4 = *(const float4*)&cls_weight[k * MC_DIM + lane * 4];
    const float  bias = cls_bias[k];

    #pragma unroll 1
    for (int b = blockIdx.x; b < B_SZ; b += RT_GRID) {
        if (tid < N_IN) sa[tid] = acts_prior[(size_t)b * N_IN + tid];

        float4 v[N_IN];
        {
            const float* vb = g_votes + (size_t)b * VOTES_PER_B + k * MC_DIM + lane * 4;
            #pragma unroll
            for (int n = 0; n < N_IN; n++)
                v[n] = *(const float4*)(vb + n * KM);
        }
        __syncthreads();

        float ra[N_IN];
        #pragma unroll
        for (int n = 0; n < N_IN; n++) ra[n] = sa[n] * (1.f / 25.f);

        float4 pose;
        #pragma unroll 1
        for (int it = 0; it < 3; ++it) {
            if (it > 0) {
                #pragma unroll
                for (int n = 0; n < N_IN; n++) {
                    float d = v[n].x * pose.x + v[n].y * pose.y
                            + v[n].z * pose.z + v[n].w * pose.w;
                    d = warp_sum(d);
                    if (lane == 0) sagree[n * K_CAPS + k] = d * AGREE_SCALE;
                }
                __syncthreads();
                if (wrp < N_IN) {
                    const float x = (lane < K_CAPS) ? sagree[wrp * K_CAPS + lane] : -1e30f;
                    const float mx = warp_max(x);
                    const float e = (lane < K_CAPS) ? __expf(x - mx) : 0.f;
                    const float ssum = warp_sum(e);
                    if (lane < K_CAPS) {
                        const float r = e / ssum;
                        sra[wrp * K_CAPS + lane] = r * sa[wrp];
                        if (it == 2)
                            out[(size_t)B_SZ * K_CAPS + (size_t)b * 175
                                + wrp * K_CAPS + lane] = r;
                    }
                }
                __syncthreads();
                #pragma unroll
                for (int n = 0; n < N_IN; n++) ra[n] = sra[n * K_CAPS + k];
            }
            pose = make_float4(0.f, 0.f, 0.f, 0.f);
            #pragma unroll
            for (int n = 0; n < N_IN; n++) {
                pose.x = fmaf(ra[n], v[n].x, pose.x);
                pose.y = fmaf(ra[n], v[n].y, pose.y);
                pose.z = fmaf(ra[n], v[n].z, pose.z);
                pose.w = fmaf(ra[n], v[n].w, pose.w);
            }
            {
                float s = pose.x + pose.y + pose.z + pose.w;
                s = warp_sum(s);
                const float mu = s * (1.f / 128.f);
                float var = (pose.x - mu) * (pose.x - mu) + (pose.y - mu) * (pose.y - mu)
                          + (pose.z - mu) * (pose.z - mu) + (pose.w - mu) * (pose.w - mu);
                var = warp_sum(var) * (1.f / 128.f);
                const float rs = rsqrtf(var + LN_EPS);
                pose.x = (pose.x - mu) * rs * g4.x + b4.x;
                pose.y = (pose.y - mu) * rs * g4.y + b4.y;
                pose.z = (pose.z - mu) * rs * g4.z + b4.z;
                pose.w = (pose.w - mu) * rs * g4.w + b4.w;
            }
        }
        {
            float d = pose.x * cw4.x + pose.y * cw4.y + pose.z * cw4.z + pose.w * cw4.w;
            d = warp_sum(d);
            if (lane == 0) out[(size_t)b * K_CAPS + k] = d + bias;
        }
    }
}

// ---------------------------------------------------------------------------
extern "C" void kernel_launch(void* const* d_in, const int* in_sizes, int n_in,
                              void* d_out, int out_size)
{
    (void)in_sizes; (void)n_in; (void)out_size;
    const float* poses = (const float*)d_in[0];
    const float* acts  = (const float*)d_in[1];
    const float* w     = (const float*)d_in[2];
    const float* gamma = (const float*)d_in[3];
    const float* beta  = (const float*)d_in[4];
    const float* clsw  = (const float*)d_in[5];
    const float* clsb  = (const float*)d_in[6];
    float* out = (float*)d_out;

    __nv_bfloat16 *pa_hi, *pa_lo, *wt_hi, *wt_lo;
    cudaGetSymbolAddress((void**)&pa_hi, g_pa_hi);
    cudaGetSymbolAddress((void**)&pa_lo, g_pa_lo);
    cudaGetSymbolAddress((void**)&wt_hi, g_wt_hi);
    cudaGetSymbolAddress((void**)&wt_lo, g_wt_lo);

    decomp_fused_kernel<<<PO_BLKS + WT_BLKS, 256>>>(poses, w, pa_hi, pa_lo, wt_hi, wt_lo);

    cudaFuncSetAttribute(votes_hmma_kernel,
                         cudaFuncAttributeMaxDynamicSharedMemorySize,
                         VOTES_SMEM);
    votes_hmma_kernel<<<dim3(25, 32, 7), 256, VOTES_SMEM>>>(pa_hi, pa_lo, wt_hi, wt_lo);

    routing_kernel<<<RT_GRID, 800>>>(acts, gamma, beta, clsw, clsb, out);
}